// round 1
// baseline (speedup 1.0000x reference)
#include <cuda_runtime.h>

#define Bsz 2048
#define Dsz 512
#define Hsz 1024
#define Ssz 100
#define KTOP 51

// Scratch (device globals — no allocations allowed)
__device__ float g_h[Bsz * Hsz];         // relu(fc1) output, 8 MB
__device__ float g_epsmean[Bsz * Dsz];   // mean over S of eps, 4 MB
__device__ float g_op[Bsz * Dsz];        // pre-topk op, 4 MB

// ---------------------------------------------------------------------------
// Kernel 1: eps_mean[b,d] = mean_s eps[s,b,d].  419 MB read, HBM-bound.
// ---------------------------------------------------------------------------
__global__ void k_epsmean(const float4* __restrict__ eps4) {
    const int nd4 = Bsz * Dsz / 4;  // 262144
    int i = blockIdx.x * blockDim.x + threadIdx.x;
    float4 a0 = make_float4(0.f, 0.f, 0.f, 0.f);
    float4 a1 = make_float4(0.f, 0.f, 0.f, 0.f);
#pragma unroll 5
    for (int s = 0; s < Ssz; s += 2) {
        float4 x = eps4[(size_t)s * nd4 + i];
        float4 y = eps4[(size_t)(s + 1) * nd4 + i];
        a0.x += x.x; a0.y += x.y; a0.z += x.z; a0.w += x.w;
        a1.x += y.x; a1.y += y.y; a1.z += y.z; a1.w += y.w;
    }
    const float inv = 1.0f / (float)Ssz;
    float4 r;
    r.x = (a0.x + a1.x) * inv;
    r.y = (a0.y + a1.y) * inv;
    r.z = (a0.z + a1.z) * inv;
    r.w = (a0.w + a1.w) * inv;
    ((float4*)g_epsmean)[i] = r;
}

// ---------------------------------------------------------------------------
// Kernel 2: g_h = relu(batch @ W1^T + b1).   M=2048 N=1024 K=512 (NT gemm)
// 128x128 block tile, BK=16, 8x8 per thread, 256 threads.
// ---------------------------------------------------------------------------
#define BM 128
#define BN 128
#define BK 16
#define TM 8
#define TN 8

__global__ __launch_bounds__(256) void k_gemm1(const float* __restrict__ A,
                                               const float* __restrict__ W,
                                               const float* __restrict__ bias) {
    __shared__ __align__(16) float As[BK][BM + 4];
    __shared__ __align__(16) float Bs[BK][BN + 4];
    const int tid = threadIdx.x;
    const int tx = tid & 15;   // 16 col groups of TN=8
    const int ty = tid >> 4;   // 16 row groups of TM=8
    const int rowBase = blockIdx.y * BM;
    const int colBase = blockIdx.x * BN;

    float acc[TM][TN];
#pragma unroll
    for (int i = 0; i < TM; i++)
#pragma unroll
        for (int j = 0; j < TN; j++) acc[i][j] = 0.f;

    for (int k0 = 0; k0 < Dsz; k0 += BK) {
#pragma unroll
        for (int f = tid; f < BM * BK / 4; f += 256) {  // 512 float4
            int r = f >> 2;
            int kq = (f & 3) << 2;
            float4 v = *(const float4*)(A + (size_t)(rowBase + r) * Dsz + k0 + kq);
            As[kq + 0][r] = v.x; As[kq + 1][r] = v.y;
            As[kq + 2][r] = v.z; As[kq + 3][r] = v.w;
        }
#pragma unroll
        for (int f = tid; f < BN * BK / 4; f += 256) {
            int r = f >> 2;
            int kq = (f & 3) << 2;
            float4 v = *(const float4*)(W + (size_t)(colBase + r) * Dsz + k0 + kq);
            Bs[kq + 0][r] = v.x; Bs[kq + 1][r] = v.y;
            Bs[kq + 2][r] = v.z; Bs[kq + 3][r] = v.w;
        }
        __syncthreads();
#pragma unroll
        for (int k = 0; k < BK; k++) {
            float a[TM], b[TN];
            *(float4*)&a[0] = *(const float4*)&As[k][ty * TM];
            *(float4*)&a[4] = *(const float4*)&As[k][ty * TM + 4];
            *(float4*)&b[0] = *(const float4*)&Bs[k][tx * TN];
            *(float4*)&b[4] = *(const float4*)&Bs[k][tx * TN + 4];
#pragma unroll
            for (int i = 0; i < TM; i++)
#pragma unroll
                for (int j = 0; j < TN; j++)
                    acc[i][j] = fmaf(a[i], b[j], acc[i][j]);
        }
        __syncthreads();
    }
#pragma unroll
    for (int i = 0; i < TM; i++) {
        int row = rowBase + ty * TM + i;
#pragma unroll
        for (int j = 0; j < TN; j += 4) {
            int col = colBase + tx * TN + j;
            float4 bv = *(const float4*)(bias + col);
            float4 v;
            v.x = fmaxf(acc[i][j + 0] + bv.x, 0.f);
            v.y = fmaxf(acc[i][j + 1] + bv.y, 0.f);
            v.z = fmaxf(acc[i][j + 2] + bv.z, 0.f);
            v.w = fmaxf(acc[i][j + 3] + bv.w, 0.f);
            *(float4*)(g_h + (size_t)row * Hsz + col) = v;
        }
    }
}

// ---------------------------------------------------------------------------
// Kernel 3: dual GEMM over h (K=1024): mu & log_var share the A tile.
// Epilogue: op = (mu + eps_mean * exp(0.5*lv)) * (batch != 0)
// 128x64(x2 outputs) block tile, 8x4x2 per thread, 256 threads.
// ---------------------------------------------------------------------------
#define BN2 64
#define TN2 4

__global__ __launch_bounds__(256) void k_gemm2(const float* __restrict__ batch,
                                               const float* __restrict__ W21,
                                               const float* __restrict__ b21,
                                               const float* __restrict__ W22,
                                               const float* __restrict__ b22) {
    __shared__ __align__(16) float As[BK][BM + 4];
    __shared__ __align__(16) float B1s[BK][BN2 + 4];
    __shared__ __align__(16) float B2s[BK][BN2 + 4];
    const int tid = threadIdx.x;
    const int tx = tid & 15;   // 16 col groups of TN2=4
    const int ty = tid >> 4;   // 16 row groups of TM=8
    const int rowBase = blockIdx.y * BM;
    const int colBase = blockIdx.x * BN2;

    float accA[TM][TN2], accB[TM][TN2];
#pragma unroll
    for (int i = 0; i < TM; i++)
#pragma unroll
        for (int j = 0; j < TN2; j++) { accA[i][j] = 0.f; accB[i][j] = 0.f; }

    for (int k0 = 0; k0 < Hsz; k0 += BK) {
#pragma unroll
        for (int f = tid; f < BM * BK / 4; f += 256) {  // A tile from g_h
            int r = f >> 2;
            int kq = (f & 3) << 2;
            float4 v = *(const float4*)(g_h + (size_t)(rowBase + r) * Hsz + k0 + kq);
            As[kq + 0][r] = v.x; As[kq + 1][r] = v.y;
            As[kq + 2][r] = v.z; As[kq + 3][r] = v.w;
        }
        {
            int f = tid;  // 256 float4 per B tile, exactly 1 per thread
            int r = f >> 2;
            int kq = (f & 3) << 2;
            float4 v1 = *(const float4*)(W21 + (size_t)(colBase + r) * Hsz + k0 + kq);
            B1s[kq + 0][r] = v1.x; B1s[kq + 1][r] = v1.y;
            B1s[kq + 2][r] = v1.z; B1s[kq + 3][r] = v1.w;
            float4 v2 = *(const float4*)(W22 + (size_t)(colBase + r) * Hsz + k0 + kq);
            B2s[kq + 0][r] = v2.x; B2s[kq + 1][r] = v2.y;
            B2s[kq + 2][r] = v2.z; B2s[kq + 3][r] = v2.w;
        }
        __syncthreads();
#pragma unroll
        for (int k = 0; k < BK; k++) {
            float a[TM], b1[TN2], b2[TN2];
            *(float4*)&a[0] = *(const float4*)&As[k][ty * TM];
            *(float4*)&a[4] = *(const float4*)&As[k][ty * TM + 4];
            *(float4*)&b1[0] = *(const float4*)&B1s[k][tx * TN2];
            *(float4*)&b2[0] = *(const float4*)&B2s[k][tx * TN2];
#pragma unroll
            for (int i = 0; i < TM; i++)
#pragma unroll
                for (int j = 0; j < TN2; j++) {
                    accA[i][j] = fmaf(a[i], b1[j], accA[i][j]);
                    accB[i][j] = fmaf(a[i], b2[j], accB[i][j]);
                }
        }
        __syncthreads();
    }

    const int col = colBase + tx * TN2;
    float4 bv1 = *(const float4*)(b21 + col);
    float4 bv2 = *(const float4*)(b22 + col);
    float bb1[4] = {bv1.x, bv1.y, bv1.z, bv1.w};
    float bb2[4] = {bv2.x, bv2.y, bv2.z, bv2.w};
#pragma unroll
    for (int i = 0; i < TM; i++) {
        int row = rowBase + ty * TM + i;
        float4 em = *(const float4*)(g_epsmean + (size_t)row * Dsz + col);
        float4 bt = *(const float4*)(batch + (size_t)row * Dsz + col);
        float e[4] = {em.x, em.y, em.z, em.w};
        float m[4] = {bt.x, bt.y, bt.z, bt.w};
        float o[4];
#pragma unroll
        for (int j = 0; j < TN2; j++) {
            float mu = accA[i][j] + bb1[j];
            float lv = accB[i][j] + bb2[j];
            float v = mu + e[j] * expf(0.5f * lv);
            o[j] = (m[j] != 0.f) ? v : 0.f;
        }
        float4 ov = make_float4(o[0], o[1], o[2], o[3]);
        *(float4*)(g_op + (size_t)row * Dsz + col) = ov;
    }
}

// ---------------------------------------------------------------------------
// Kernel 4: stable top-51 of 512 per row.  One warp per row; radix-select
// on order-preserving uint keys; tie-break = lowest index (matches lax.top_k).
// ---------------------------------------------------------------------------
__global__ void k_topk(float* __restrict__ out) {
    const int warp = threadIdx.x >> 5;
    const int lane = threadIdx.x & 31;
    const int row = blockIdx.x * 8 + warp;
    const float* src = g_op + (size_t)row * Dsz;

    float v[16];
    unsigned u[16];
#pragma unroll
    for (int i = 0; i < 16; i++) {
        v[i] = src[lane + 32 * i];
        unsigned b = __float_as_uint(v[i]);
        u[i] = (b & 0x80000000u) ? ~b : (b | 0x80000000u);
    }

    // Radix-select: largest T with count(u >= T) >= KTOP  -> key of 51st largest
    unsigned T = 0u;
#pragma unroll 1
    for (int bit = 31; bit >= 0; --bit) {
        unsigned cand = T | (1u << bit);
        int c = 0;
#pragma unroll
        for (int i = 0; i < 16; i++) c += (u[i] >= cand) ? 1 : 0;
        c = (int)__reduce_add_sync(0xffffffffu, (unsigned)c);
        if (c >= KTOP) T = cand;
    }

    int g = 0;
#pragma unroll
    for (int i = 0; i < 16; i++) g += (u[i] > T) ? 1 : 0;
    g = (int)__reduce_add_sync(0xffffffffu, (unsigned)g);

    float* dst = out + (size_t)row * Dsz;
    int pre = g;  // strictly-greater count; equals admitted in index order
#pragma unroll
    for (int i = 0; i < 16; i++) {
        unsigned bal = __ballot_sync(0xffffffffu, u[i] == T);
        int before = pre + __popc(bal & ((1u << lane) - 1u));
        bool keep = (u[i] > T) || ((u[i] == T) && (before < KTOP));
        dst[lane + 32 * i] = keep ? v[i] : 0.f;
        pre += __popc(bal);
    }
}

// ---------------------------------------------------------------------------
extern "C" void kernel_launch(void* const* d_in, const int* in_sizes, int n_in,
                              void* d_out, int out_size) {
    const float* batch = (const float*)d_in[0];
    const float* W1    = (const float*)d_in[1];
    const float* b1    = (const float*)d_in[2];
    const float* W21   = (const float*)d_in[3];
    const float* b21   = (const float*)d_in[4];
    const float* W22   = (const float*)d_in[5];
    const float* b22   = (const float*)d_in[6];
    const float* eps   = (const float*)d_in[7];
    float* out = (float*)d_out;

    k_epsmean<<<(Bsz * Dsz / 4) / 256, 256>>>((const float4*)eps);
    k_gemm1<<<dim3(Hsz / BN, Bsz / BM), 256>>>(batch, W1, b1);
    k_gemm2<<<dim3(Dsz / BN2, Bsz / BM), 256>>>(batch, W21, b21, W22, b22);
    k_topk<<<Bsz / 8, 256>>>(out);
}

// round 4
// speedup vs baseline: 1.2987x; 1.2987x over previous
#include <cuda_runtime.h>
#include <cstdint>

#define Bsz 2048
#define Dsz 512
#define Hsz 1024
#define Ssz 100
#define KTOP 51

// Scratch (device globals — no allocations allowed)
__device__ float g_h[Bsz * Hsz];         // relu(fc1) output, 8 MB
__device__ float g_epsmean[Bsz * Dsz];   // mean over S of eps, 4 MB
__device__ float g_op[Bsz * Dsz];        // pre-topk op, 4 MB

// ---------------------------------------------------------------------------
// Helpers
// ---------------------------------------------------------------------------
__device__ __forceinline__ uint32_t smem_u32(const void* p) {
    uint32_t a;
    asm("{ .reg .u64 t; cvta.to.shared.u64 t, %1; cvt.u32.u64 %0, t; }" : "=r"(a) : "l"(p));
    return a;
}

#define CP16(dst, src) \
    asm volatile("cp.async.cg.shared.global [%0], [%1], 16;" :: "r"(dst), "l"(src))
#define CP_COMMIT() asm volatile("cp.async.commit_group;" ::: "memory")
#define CP_WAIT1()  asm volatile("cp.async.wait_group 1;" ::: "memory")
#define CP_WAIT0()  asm volatile("cp.async.wait_group 0;" ::: "memory")

__device__ __forceinline__ uint32_t f2tf(float x) {
    uint32_t u;
    asm("cvt.rna.tf32.f32 %0, %1;" : "=r"(u) : "f"(x));
    return u;
}

// hi/lo split for 3xTF32 error compensation
__device__ __forceinline__ void split_tf(float x, uint32_t& hi, uint32_t& lo) {
    hi = f2tf(x);
    lo = f2tf(x - __uint_as_float(hi));
}

__device__ __forceinline__ void mma8(float* d, const uint32_t* a, const uint32_t* b) {
    asm volatile(
        "mma.sync.aligned.m16n8k8.row.col.f32.tf32.tf32.f32 "
        "{%0,%1,%2,%3}, {%4,%5,%6,%7}, {%8,%9}, {%0,%1,%2,%3};\n"
        : "+f"(d[0]), "+f"(d[1]), "+f"(d[2]), "+f"(d[3])
        : "r"(a[0]), "r"(a[1]), "r"(a[2]), "r"(a[3]), "r"(b[0]), "r"(b[1]));
}

#define LDA 36  // 32 floats + 4 pad: conflict-free fragment LDS

// ---------------------------------------------------------------------------
// Kernel 1: eps_mean[b,d] = mean_s eps[s,b,d].  419 MB read, HBM-bound.
// ---------------------------------------------------------------------------
__global__ void k_epsmean(const float4* __restrict__ eps4) {
    const int nd4 = Bsz * Dsz / 4;
    int i = blockIdx.x * blockDim.x + threadIdx.x;
    float4 a0 = make_float4(0.f, 0.f, 0.f, 0.f);
    float4 a1 = make_float4(0.f, 0.f, 0.f, 0.f);
#pragma unroll 5
    for (int s = 0; s < Ssz; s += 2) {
        float4 x = eps4[(size_t)s * nd4 + i];
        float4 y = eps4[(size_t)(s + 1) * nd4 + i];
        a0.x += x.x; a0.y += x.y; a0.z += x.z; a0.w += x.w;
        a1.x += y.x; a1.y += y.y; a1.z += y.z; a1.w += y.w;
    }
    const float inv = 1.0f / (float)Ssz;
    float4 r;
    r.x = (a0.x + a1.x) * inv;
    r.y = (a0.y + a1.y) * inv;
    r.z = (a0.z + a1.z) * inv;
    r.w = (a0.w + a1.w) * inv;
    ((float4*)g_epsmean)[i] = r;
}

// ---------------------------------------------------------------------------
// Kernel 2: g_h = relu(batch @ W1^T + b1) via 3xTF32 mma.sync.
// 128x128 CTA tile, BK=32, cp.async double-buffered, warp tile 64x32.
// ---------------------------------------------------------------------------
__global__ void __launch_bounds__(256, 1)
k_gemm1(const float* __restrict__ A, const float* __restrict__ W,
        const float* __restrict__ bias) {
    extern __shared__ __align__(16) float sm[];
    // layout (floats): A0 @0, A1 @4608, B0 @9216, B1 @13824
    const uint32_t sbase = smem_u32(sm);
    const int tid = threadIdx.x, lane = tid & 31, wid = tid >> 5;
    const int warpM = wid >> 2, warpN = wid & 3;
    const int grp = lane >> 2, tig = lane & 3;
    const int rowBase = blockIdx.y * 128, colBase = blockIdx.x * 128;

    float acc[4][4][4];
#pragma unroll
    for (int mi = 0; mi < 4; mi++)
#pragma unroll
        for (int ni = 0; ni < 4; ni++)
#pragma unroll
            for (int j = 0; j < 4; j++) acc[mi][ni][j] = 0.f;

#define G1_LOAD(c, q)                                                              \
    do {                                                                           \
        int k0 = (c) * 32;                                                         \
        uint32_t sa = sbase + (q) * 4608 * 4;                                      \
        uint32_t sb = sbase + (9216 + (q) * 4608) * 4;                             \
        _Pragma("unroll")                                                          \
        for (int it = 0; it < 4; it++) {                                           \
            int f = tid + it * 256;                                                \
            int r = f >> 3, c4 = f & 7;                                            \
            CP16(sa + (r * LDA + c4 * 4) * 4,                                      \
                 A + (size_t)(rowBase + r) * Dsz + k0 + c4 * 4);                   \
            CP16(sb + (r * LDA + c4 * 4) * 4,                                      \
                 W + (size_t)(colBase + r) * Dsz + k0 + c4 * 4);                   \
        }                                                                          \
        CP_COMMIT();                                                               \
    } while (0)

    G1_LOAD(0, 0);
    for (int c = 0; c < 16; c++) {
        const int q = c & 1;
        if (c + 1 < 16) { G1_LOAD(c + 1, q ^ 1); CP_WAIT1(); }
        else            { CP_WAIT0(); }
        __syncthreads();
        const float* a_s = sm + q * 4608;
        const float* b_s = sm + 9216 + q * 4608;
#pragma unroll
        for (int kk = 0; kk < 4; kk++) {
            const int kc = kk * 8 + tig;
            uint32_t ah[4][4], al[4][4], bh[4][2], bl[4][2];
#pragma unroll
            for (int mi = 0; mi < 4; mi++) {
                int r = warpM * 64 + mi * 16 + grp;
                split_tf(a_s[r * LDA + kc],           ah[mi][0], al[mi][0]);
                split_tf(a_s[(r + 8) * LDA + kc],     ah[mi][1], al[mi][1]);
                split_tf(a_s[r * LDA + kc + 4],       ah[mi][2], al[mi][2]);
                split_tf(a_s[(r + 8) * LDA + kc + 4], ah[mi][3], al[mi][3]);
            }
#pragma unroll
            for (int ni = 0; ni < 4; ni++) {
                int n = warpN * 32 + ni * 8 + grp;
                split_tf(b_s[n * LDA + kc],     bh[ni][0], bl[ni][0]);
                split_tf(b_s[n * LDA + kc + 4], bh[ni][1], bl[ni][1]);
            }
#pragma unroll
            for (int mi = 0; mi < 4; mi++)
#pragma unroll
                for (int ni = 0; ni < 4; ni++) {
                    mma8(acc[mi][ni], ah[mi], bh[ni]);
                    mma8(acc[mi][ni], ah[mi], bl[ni]);
                    mma8(acc[mi][ni], al[mi], bh[ni]);
                }
        }
        __syncthreads();
    }
#undef G1_LOAD

#pragma unroll
    for (int mi = 0; mi < 4; mi++) {
        int r0 = rowBase + warpM * 64 + mi * 16 + grp;
#pragma unroll
        for (int ni = 0; ni < 4; ni++) {
            int c = colBase + warpN * 32 + ni * 8 + tig * 2;
            float b0 = __ldg(bias + c), b1 = __ldg(bias + c + 1);
            float2 v0 = make_float2(fmaxf(acc[mi][ni][0] + b0, 0.f),
                                    fmaxf(acc[mi][ni][1] + b1, 0.f));
            float2 v1 = make_float2(fmaxf(acc[mi][ni][2] + b0, 0.f),
                                    fmaxf(acc[mi][ni][3] + b1, 0.f));
            *(float2*)(g_h + (size_t)r0 * Hsz + c) = v0;
            *(float2*)(g_h + (size_t)(r0 + 8) * Hsz + c) = v1;
        }
    }
}

// ---------------------------------------------------------------------------
// Kernel 3: fused dual GEMM (mu & log_var) via 3xTF32 mma.sync.
// 128(M)x128(N) CTA tile over K=1024; B rows 0-63 = W21, rows 64-127 = W22
// for the same 64 output cols.  Epilogue pairs mu/lv via smem staging:
// op = (mu + eps_mean * exp(0.5*lv)) * (batch != 0).
// ---------------------------------------------------------------------------
__global__ void __launch_bounds__(256, 1)
k_gemm2(const float* __restrict__ batch,
        const float* __restrict__ W21, const float* __restrict__ b21,
        const float* __restrict__ W22, const float* __restrict__ b22) {
    extern __shared__ __align__(16) float sm[];
    // layout (floats): A0 @0, A1 @4608, B0 @9216, B1 @13824
    const uint32_t sbase = smem_u32(sm);
    const int tid = threadIdx.x, lane = tid & 31, wid = tid >> 5;
    const int warpM = wid >> 2, warpN = wid & 3;
    const int grp = lane >> 2, tig = lane & 3;
    const int rowBase = blockIdx.y * 128, colBase = blockIdx.x * 64;

    float acc[4][4][4];
#pragma unroll
    for (int mi = 0; mi < 4; mi++)
#pragma unroll
        for (int ni = 0; ni < 4; ni++)
#pragma unroll
            for (int j = 0; j < 4; j++) acc[mi][ni][j] = 0.f;

#define G2_LOAD(c, q)                                                              \
    do {                                                                           \
        int k0 = (c) * 32;                                                         \
        uint32_t sa = sbase + (q) * 4608 * 4;                                      \
        uint32_t sb = sbase + (9216 + (q) * 4608) * 4;                             \
        _Pragma("unroll")                                                          \
        for (int it = 0; it < 4; it++) {                                           \
            int f = tid + it * 256;                                                \
            int r = f >> 3, c4 = f & 7;                                            \
            CP16(sa + (r * LDA + c4 * 4) * 4,                                      \
                 g_h + (size_t)(rowBase + r) * Hsz + k0 + c4 * 4);                 \
            const float* src = (r < 64)                                            \
                ? (W21 + (size_t)(colBase + r) * Hsz)                              \
                : (W22 + (size_t)(colBase + r - 64) * Hsz);                        \
            CP16(sb + (r * LDA + c4 * 4) * 4, src + k0 + c4 * 4);                  \
        }                                                                          \
        CP_COMMIT();                                                               \
    } while (0)

    G2_LOAD(0, 0);
    for (int c = 0; c < 32; c++) {
        const int q = c & 1;
        if (c + 1 < 32) { G2_LOAD(c + 1, q ^ 1); CP_WAIT1(); }
        else            { CP_WAIT0(); }
        __syncthreads();
        const float* a_s = sm + q * 4608;
        const float* b_s = sm + 9216 + q * 4608;
#pragma unroll
        for (int kk = 0; kk < 4; kk++) {
            const int kc = kk * 8 + tig;
            uint32_t ah[4][4], al[4][4], bh[4][2], bl[4][2];
#pragma unroll
            for (int mi = 0; mi < 4; mi++) {
                int r = warpM * 64 + mi * 16 + grp;
                split_tf(a_s[r * LDA + kc],           ah[mi][0], al[mi][0]);
                split_tf(a_s[(r + 8) * LDA + kc],     ah[mi][1], al[mi][1]);
                split_tf(a_s[r * LDA + kc + 4],       ah[mi][2], al[mi][2]);
                split_tf(a_s[(r + 8) * LDA + kc + 4], ah[mi][3], al[mi][3]);
            }
#pragma unroll
            for (int ni = 0; ni < 4; ni++) {
                int n = warpN * 32 + ni * 8 + grp;
                split_tf(b_s[n * LDA + kc],     bh[ni][0], bl[ni][0]);
                split_tf(b_s[n * LDA + kc + 4], bh[ni][1], bl[ni][1]);
            }
#pragma unroll
            for (int mi = 0; mi < 4; mi++)
#pragma unroll
                for (int ni = 0; ni < 4; ni++) {
                    mma8(acc[mi][ni], ah[mi], bh[ni]);
                    mma8(acc[mi][ni], ah[mi], bl[ni]);
                    mma8(acc[mi][ni], al[mi], bh[ni]);
                }
        }
        __syncthreads();
    }
#undef G2_LOAD

    // Stage D (128 x 128) into smem so threads can pair mu (cols 0-63) with
    // log_var (cols 64-127).  128*132 = 16896 floats <= 18432 available.
    float* Dsm = sm;
#pragma unroll
    for (int mi = 0; mi < 4; mi++) {
        int r = warpM * 64 + mi * 16 + grp;
#pragma unroll
        for (int ni = 0; ni < 4; ni++) {
            int n = warpN * 32 + ni * 8 + tig * 2;
            *(float2*)&Dsm[r * 132 + n] = make_float2(acc[mi][ni][0], acc[mi][ni][1]);
            *(float2*)&Dsm[(r + 8) * 132 + n] = make_float2(acc[mi][ni][2], acc[mi][ni][3]);
        }
    }
    __syncthreads();

#pragma unroll
    for (int it = 0; it < 8; it++) {
        int f = tid + it * 256;       // 2048 float4 = 128 rows x 16 quad-cols
        int r = f >> 4, c4 = f & 15;
        int gr = rowBase + r, gc = colBase + c4 * 4;
        float4 mu = *(float4*)&Dsm[r * 132 + c4 * 4];
        float4 lv = *(float4*)&Dsm[r * 132 + 64 + c4 * 4];
        float4 bv1 = __ldg((const float4*)(b21 + gc));
        float4 bv2 = __ldg((const float4*)(b22 + gc));
        float4 em = __ldg((const float4*)(g_epsmean + (size_t)gr * Dsz + gc));
        float4 bt = __ldg((const float4*)(batch + (size_t)gr * Dsz + gc));
        float4 o;
        float m0 = mu.x + bv1.x, l0 = lv.x + bv2.x;
        float m1 = mu.y + bv1.y, l1 = lv.y + bv2.y;
        float m2 = mu.z + bv1.z, l2 = lv.z + bv2.z;
        float m3 = mu.w + bv1.w, l3 = lv.w + bv2.w;
        o.x = (bt.x != 0.f) ? (m0 + em.x * expf(0.5f * l0)) : 0.f;
        o.y = (bt.y != 0.f) ? (m1 + em.y * expf(0.5f * l1)) : 0.f;
        o.z = (bt.z != 0.f) ? (m2 + em.z * expf(0.5f * l2)) : 0.f;
        o.w = (bt.w != 0.f) ? (m3 + em.w * expf(0.5f * l3)) : 0.f;
        *(float4*)(g_op + (size_t)gr * Dsz + gc) = o;
    }
}

// ---------------------------------------------------------------------------
// Kernel 4: stable top-51 of 512 per row.  One warp per TWO rows (ILP),
// radix-select with both counts packed into one __reduce_add_sync.
// ---------------------------------------------------------------------------
__global__ void k_topk(float* __restrict__ out) {
    const int warp = threadIdx.x >> 5;
    const int lane = threadIdx.x & 31;
    const int row0 = blockIdx.x * 16 + warp * 2;

    float v[2][16];
    unsigned u[2][16];
#pragma unroll
    for (int rr = 0; rr < 2; rr++) {
        const float* src = g_op + (size_t)(row0 + rr) * Dsz;
#pragma unroll
        for (int i = 0; i < 16; i++) {
            v[rr][i] = src[lane + 32 * i];
            unsigned b = __float_as_uint(v[rr][i]);
            u[rr][i] = (b & 0x80000000u) ? ~b : (b | 0x80000000u);
        }
    }

    unsigned T0 = 0u, T1 = 0u;
#pragma unroll 1
    for (int bit = 31; bit >= 0; --bit) {
        unsigned cand0 = T0 | (1u << bit);
        unsigned cand1 = T1 | (1u << bit);
        int c0 = 0, c1 = 0;
#pragma unroll
        for (int i = 0; i < 16; i++) {
            c0 += (u[0][i] >= cand0) ? 1 : 0;
            c1 += (u[1][i] >= cand1) ? 1 : 0;
        }
        unsigned s = __reduce_add_sync(0xffffffffu, (unsigned)(c0 | (c1 << 16)));
        if ((s & 0xffffu) >= KTOP) T0 = cand0;
        if ((s >> 16) >= KTOP) T1 = cand1;
    }

    unsigned T[2] = {T0, T1};
#pragma unroll
    for (int rr = 0; rr < 2; rr++) {
        int g = 0;
#pragma unroll
        for (int i = 0; i < 16; i++) g += (u[rr][i] > T[rr]) ? 1 : 0;
        g = (int)__reduce_add_sync(0xffffffffu, (unsigned)g);

        float* dst = out + (size_t)(row0 + rr) * Dsz;
        int pre = g;
#pragma unroll
        for (int i = 0; i < 16; i++) {
            unsigned bal = __ballot_sync(0xffffffffu, u[rr][i] == T[rr]);
            int before = pre + __popc(bal & ((1u << lane) - 1u));
            bool keep = (u[rr][i] > T[rr]) || ((u[rr][i] == T[rr]) && (before < KTOP));
            dst[lane + 32 * i] = keep ? v[rr][i] : 0.f;
            pre += __popc(bal);
        }
    }
}

// ---------------------------------------------------------------------------
extern "C" void kernel_launch(void* const* d_in, const int* in_sizes, int n_in,
                              void* d_out, int out_size) {
    const float* batch = (const float*)d_in[0];
    const float* W1    = (const float*)d_in[1];
    const float* b1    = (const float*)d_in[2];
    const float* W21   = (const float*)d_in[3];
    const float* b21   = (const float*)d_in[4];
    const float* W22   = (const float*)d_in[5];
    const float* b22   = (const float*)d_in[6];
    const float* eps   = (const float*)d_in[7];
    float* out = (float*)d_out;

    const int smem = 18432 * 4;  // 73728 B
    cudaFuncSetAttribute(k_gemm1, cudaFuncAttributeMaxDynamicSharedMemorySize, smem);
    cudaFuncSetAttribute(k_gemm2, cudaFuncAttributeMaxDynamicSharedMemorySize, smem);

    k_epsmean<<<(Bsz * Dsz / 4) / 256, 256>>>((const float4*)eps);
    k_gemm1<<<dim3(Hsz / 128, Bsz / 128), 256, smem>>>(batch, W1, b1);
    k_gemm2<<<dim3(Dsz / 64, Bsz / 128), 256, smem>>>(batch, W21, b21, W22, b22);
    k_topk<<<Bsz / 16, 256>>>(out);
}